// round 5
// baseline (speedup 1.0000x reference)
#include <cuda_runtime.h>
#include <cuda_bf16.h>
#include <mma.h>

using namespace nvcuda;
typedef __nv_bfloat16 bf16;

#define OFF_H0 0
#define OFF_H1 1048576            // 1024*1024
#define OFF_H2 1310720            // +1024*256
#define OFF_H3 1376256            // +1024*64

// scratch (static device memory; no allocations anywhere)
__device__ bf16  g_H[1392640];
__device__ float g_sumexp[4096];

__global__ void zero_kernel() {
    int i = blockIdx.x * blockDim.x + threadIdx.x;
    if (i < 4096) g_sumexp[i] = 0.0f;
}

// ---------------------------------------------------------------------------
// cp.async helpers
// ---------------------------------------------------------------------------
__device__ __forceinline__ void cp16(bf16* dst, const bf16* src) {
    unsigned d = (unsigned)__cvta_generic_to_shared(dst);
    asm volatile("cp.async.cg.shared.global [%0], [%1], 16;" :: "r"(d), "l"(src));
}
#define CP_COMMIT() asm volatile("cp.async.commit_group;")
#define CP_WAIT0()  asm volatile("cp.async.wait_group 0;")

// ---------------------------------------------------------------------------
// Unified vocab GEMM + fused exp-sum.
//   Block: 64 vocab rows (weight slab resident in smem, bf16, loaded once),
//          loops all 8 m-tiles of 128 tokens.
//   A (=H, bf16) streamed per chunk via cp.async, 2-stage double buffer.
//   128 threads = 4 warps, warp tile 64x32 (acc[4][2]).
//   Epilogue: per-warp 32x32 C patches -> exp + bias -> atomicAdd per row.
// smem: Bs[64*KP] | As0 | As1 [128*APC each] | Cp[4*32*32 f32] | bias[64]
// ---------------------------------------------------------------------------
template<int K>
__global__ __launch_bounds__(128) void vocab_kernel(
        int h_off, const float* __restrict__ W, const float* __restrict__ W2,
        const float* __restrict__ bias, const float* __restrict__ bias2,
        int split, int V, int cidx)
{
    constexpr int KP    = K + 8;
    constexpr int CHUNK = (K >= 512) ? 128 : (K > 64 ? 64 : K);
    constexpr int NC    = K / CHUNK;          // 8, 4, 1, 1
    constexpr int APC   = CHUNK + 8;
    constexpr int VPT   = (128 * CHUNK / 8) / 128;  // 16B vectors per thread
    constexpr int VR    = CHUNK / 8;          // 16B vectors per row

    extern __shared__ __align__(16) char smem[];
    bf16*  Bs     = (bf16*)smem;
    bf16*  As0    = Bs + 64 * KP;
    bf16*  As1    = As0 + 128 * APC;
    float* Cp     = (float*)(As1 + 128 * APC);
    float* bias_s = Cp + 4 * 32 * 32;

    const int tid = threadIdx.x, warpId = tid >> 5, lane = tid & 31;
    const int wm2 = warpId >> 1, wn = warpId & 1;
    const int n0 = blockIdx.x * 64;
    const bf16* __restrict__ H = g_H + h_off;

    auto cp_chunk = [&](bf16* As, int mt, int kc) {
        const bf16* src = H + (size_t)(mt * 128) * K + kc * CHUNK;
        #pragma unroll
        for (int i = 0; i < VPT; i++) {
            int idx = tid + i * 128;
            int r = idx / VR, q = idx % VR;
            cp16(As + r * APC + q * 8, src + (size_t)r * K + q * 8);
        }
    };

    // prologue: start chunk (0,0) immediately; it overlaps the B-slab load
    cp_chunk(As0, 0, 0);
    CP_COMMIT();

    if (tid < 64) {
        int v = n0 + tid;
        float bv = 0.0f;
        if (v < split)  bv = bias[v];
        else if (v < V) bv = bias2[v - split];
        bias_s[tid] = bv;
    }
    // weight slab: fp32 -> bf16, once per block
    for (int idx = tid; idx < 64 * K / 4; idx += 128) {
        int r = idx / (K / 4), q = idx % (K / 4);
        int v = n0 + r;
        float4 val = make_float4(0.f, 0.f, 0.f, 0.f);
        if (v < split)  val = *(const float4*)(W + (size_t)v * K + q * 4);
        else if (v < V) val = *(const float4*)(W2 + (size_t)(v - split) * K + q * 4);
        __nv_bfloat162 lo = __floats2bfloat162_rn(val.x, val.y);
        __nv_bfloat162 hi = __floats2bfloat162_rn(val.z, val.w);
        uint2 pk; pk.x = *(unsigned*)&lo; pk.y = *(unsigned*)&hi;
        *(uint2*)(Bs + r * KP + q * 4) = pk;
    }

    int pb = 0;   // parity of current chunk buffer
    for (int mt = 0; mt < 8; mt++) {
        wmma::fragment<wmma::accumulator, 16, 16, 16, float> acc[4][2];
        #pragma unroll
        for (int i = 0; i < 4; i++)
            #pragma unroll
            for (int j = 0; j < 2; j++) wmma::fill_fragment(acc[i][j], 0.0f);

        for (int kc = 0; kc < NC; kc++) {
            CP_WAIT0();
            __syncthreads();   // chunk (mt,kc) in buf[pb] ready; prior mma done

            // issue next chunk into the other buffer
            if (kc + 1 < NC)      cp_chunk(pb ? As0 : As1, mt, kc + 1);
            else if (mt + 1 < 8)  cp_chunk(pb ? As0 : As1, mt + 1, 0);
            CP_COMMIT();       // empty group ok on last chunk

            const bf16* As = pb ? As1 : As0;
            #pragma unroll
            for (int kk = 0; kk < CHUNK; kk += 16) {
                wmma::fragment<wmma::matrix_a, 16, 16, 16, bf16, wmma::row_major> af[4];
                wmma::fragment<wmma::matrix_b, 16, 16, 16, bf16, wmma::col_major> bfr[2];
                #pragma unroll
                for (int i = 0; i < 4; i++)
                    wmma::load_matrix_sync(af[i], As + (wm2 * 64 + i * 16) * APC + kk, APC);
                #pragma unroll
                for (int j = 0; j < 2; j++)
                    wmma::load_matrix_sync(bfr[j],
                        Bs + (wn * 32 + j * 16) * KP + kc * CHUNK + kk, KP);
                #pragma unroll
                for (int i = 0; i < 4; i++)
                    #pragma unroll
                    for (int j = 0; j < 2; j++)
                        wmma::mma_sync(acc[i][j], af[i], bfr[j], acc[i][j]);
            }
            pb ^= 1;
        }

        // epilogue: two 32x32 halves per warp through the private Cp patch
        float* cp = Cp + warpId * 32 * 32;
        #pragma unroll
        for (int h = 0; h < 2; h++) {
            #pragma unroll
            for (int j = 0; j < 2; j++) {
                wmma::store_matrix_sync(cp + j * 16,             acc[2*h+0][j], 32,
                                        wmma::mem_row_major);
                wmma::store_matrix_sync(cp + 16 * 32 + j * 16,   acc[2*h+1][j], 32,
                                        wmma::mem_row_major);
            }
            __syncwarp();
            float s = 0.0f;
            #pragma unroll
            for (int c = 0; c < 32; c++) {
                int cc = (c + lane) & 31;
                int v = n0 + wn * 32 + cc;
                if (v < V) s += __expf(cp[lane * 32 + cc] + bias_s[wn * 32 + cc]);
            }
            int row_g = mt * 128 + wm2 * 64 + h * 32 + lane;
            atomicAdd(&g_sumexp[cidx * 1024 + row_g], s);
            __syncwarp();
        }
    }
}

// ---------------------------------------------------------------------------
// Fused projection GEMM: 22 n-tiles across the 4 projections, 8 m-tiles.
// H[m,n] = sum_k hidden[m,k] * proj[k,n]; bf16 out to g_H.
// ---------------------------------------------------------------------------
#define AP 40
#define BPP 72
#define CPJ 68

__global__ __launch_bounds__(256) void proj_kernel(const float* __restrict__ A,
        const float* __restrict__ P0, const float* __restrict__ P1,
        const float* __restrict__ P2, const float* __restrict__ P3)
{
    __shared__ __align__(16) float s_c[128 * CPJ];
    bf16* As = (bf16*)s_c;
    bf16* Bs = As + 128 * AP;

    int bx = blockIdx.x;
    const float* B; int Nout, h_off, n0;
    if (bx < 16)       { B = P0; Nout = 1024; h_off = OFF_H0; n0 = bx * 64; }
    else if (bx < 20)  { B = P1; Nout = 256;  h_off = OFF_H1; n0 = (bx - 16) * 64; }
    else if (bx == 20) { B = P2; Nout = 64;   h_off = OFF_H2; n0 = 0; }
    else               { B = P3; Nout = 16;   h_off = OFF_H3; n0 = 0; }

    const int tid = threadIdx.x;
    const int warpId = tid >> 5;
    const int wm = warpId & 3, wn = warpId >> 2;
    const int m0 = blockIdx.y * 128;
    const int K = 1024;

    wmma::fragment<wmma::accumulator, 16, 16, 16, float> acc[2][2];
    #pragma unroll
    for (int i = 0; i < 2; i++)
        #pragma unroll
        for (int j = 0; j < 2; j++) wmma::fill_fragment(acc[i][j], 0.0f);

    for (int kt = 0; kt < K; kt += 32) {
        #pragma unroll
        for (int i = 0; i < 4; i++) {
            int idx = tid + i * 256;
            int r = idx >> 3, kq = (idx & 7) << 2;
            float4 v = *(const float4*)(A + (size_t)(m0 + r) * K + kt + kq);
            bf16* d = As + r * AP + kq;
            d[0] = __float2bfloat16(v.x); d[1] = __float2bfloat16(v.y);
            d[2] = __float2bfloat16(v.z); d[3] = __float2bfloat16(v.w);
        }
        #pragma unroll
        for (int i = 0; i < 2; i++) {
            int idx = tid + i * 256;
            int kr = idx >> 4, nq = (idx & 15) << 2;
            int n = n0 + nq;
            float4 v = make_float4(0.f, 0.f, 0.f, 0.f);
            if (n < Nout) v = *(const float4*)(B + (size_t)(kt + kr) * Nout + n);
            bf16* d = Bs + kr * BPP + nq;
            d[0] = __float2bfloat16(v.x); d[1] = __float2bfloat16(v.y);
            d[2] = __float2bfloat16(v.z); d[3] = __float2bfloat16(v.w);
        }
        __syncthreads();
        #pragma unroll
        for (int kk = 0; kk < 32; kk += 16) {
            wmma::fragment<wmma::matrix_a, 16, 16, 16, bf16, wmma::row_major> af[2];
            wmma::fragment<wmma::matrix_b, 16, 16, 16, bf16, wmma::row_major> bfr[2];
            #pragma unroll
            for (int i = 0; i < 2; i++)
                wmma::load_matrix_sync(af[i], As + (wm * 32 + i * 16) * AP + kk, AP);
            #pragma unroll
            for (int j = 0; j < 2; j++)
                wmma::load_matrix_sync(bfr[j], Bs + kk * BPP + wn * 32 + j * 16, BPP);
            #pragma unroll
            for (int i = 0; i < 2; i++)
                #pragma unroll
                for (int j = 0; j < 2; j++)
                    wmma::mma_sync(acc[i][j], af[i], bfr[j], acc[i][j]);
        }
        __syncthreads();
    }

    #pragma unroll
    for (int i = 0; i < 2; i++)
        #pragma unroll
        for (int j = 0; j < 2; j++)
            wmma::store_matrix_sync(s_c + (wm * 32 + i * 16) * CPJ + wn * 32 + j * 16,
                                    acc[i][j], CPJ, wmma::mem_row_major);
    __syncthreads();

    bf16* H = g_H + h_off;
    for (int idx = tid; idx < 128 * 64; idx += 256) {
        int r = idx >> 6, c = idx & 63;
        int n = n0 + c;
        if (n < Nout)
            H[(size_t)(m0 + r) * Nout + n] = __float2bfloat16(s_c[r * CPJ + c]);
    }
}

// ---------------------------------------------------------------------------
// Finalize: per-row target logit + combine with logsumexps. One warp per row.
// ---------------------------------------------------------------------------
__device__ __forceinline__ float wdot(const bf16* h, const float* w, int K, int lane) {
    float s = 0.0f;
    for (int k = lane; k < K; k += 32)
        s += __bfloat162float(h[k]) * w[k];
    #pragma unroll
    for (int o = 16; o; o >>= 1) s += __shfl_xor_sync(0xffffffffu, s, o);
    return s;
}

__global__ __launch_bounds__(256) void finalize_kernel(const int* __restrict__ target,
    const float* __restrict__ head_w,   const float* __restrict__ head_b,
    const float* __restrict__ cluster_w, const float* __restrict__ cluster_b,
    const float* __restrict__ w1, const float* __restrict__ b1,
    const float* __restrict__ w2, const float* __restrict__ b2,
    const float* __restrict__ w3, const float* __restrict__ b3,
    float* __restrict__ out)
{
    int warpId = threadIdx.x >> 5, lane = threadIdx.x & 31;
    int row = blockIdx.x * 8 + warpId;
    if (row >= 1024) return;

    const bf16* h0 = g_H + (size_t)row * 1024;

    float cl[3];
    #pragma unroll
    for (int j = 0; j < 3; j++)
        cl[j] = wdot(h0, cluster_w + j * 1024, 1024, lane) + cluster_b[j];

    float lse0 = logf(g_sumexp[row]);
    int t = target[row];
    float lp;
    if (t < 20000) {
        float s = wdot(h0, head_w + (size_t)t * 1024, 1024, lane) + head_b[t];
        lp = s - lse0;
    } else if (t < 40000) {
        int ti = t - 20000;
        const bf16* h = g_H + OFF_H1 + (size_t)row * 256;
        float s = wdot(h, w1 + (size_t)ti * 256, 256, lane) + b1[ti];
        lp = (cl[2] - lse0) + (s - logf(g_sumexp[1024 + row]));
    } else if (t < 200000) {
        int ti = t - 40000;
        const bf16* h = g_H + OFF_H2 + (size_t)row * 64;
        float s = wdot(h, w2 + (size_t)ti * 64, 64, lane) + b2[ti];
        lp = (cl[1] - lse0) + (s - logf(g_sumexp[2048 + row]));
    } else {
        int ti = t - 200000;
        const bf16* h = g_H + OFF_H3 + (size_t)row * 16;
        float s = wdot(h, w3 + (size_t)ti * 16, 16, lane) + b3[ti];
        lp = (cl[0] - lse0) + (s - logf(g_sumexp[3072 + row]));
    }
    if (lane == 0) out[row] = -lp;
}

// ---------------------------------------------------------------------------
extern "C" void kernel_launch(void* const* d_in, const int* in_sizes, int n_in,
                              void* d_out, int out_size)
{
    const float* hidden    = (const float*)d_in[0];
    const int*   target    = (const int*)  d_in[1];
    const float* head_w    = (const float*)d_in[2];
    const float* head_b    = (const float*)d_in[3];
    const float* cluster_w = (const float*)d_in[4];
    const float* cluster_b = (const float*)d_in[5];
    const float* proj0     = (const float*)d_in[6];
    const float* proj1     = (const float*)d_in[7];
    const float* proj2     = (const float*)d_in[8];
    const float* proj3     = (const float*)d_in[9];
    const float* w1        = (const float*)d_in[10];
    const float* b1        = (const float*)d_in[11];
    const float* w2        = (const float*)d_in[12];
    const float* b2        = (const float*)d_in[13];
    const float* w3        = (const float*)d_in[14];
    const float* b3        = (const float*)d_in[15];
    float* out = (float*)d_out;

    // dynamic smem: Bs(64*(K+8)*2) + As(2*128*(CHUNK+8)*2) + Cp(16384) + bias(256)
    const int SZ_HEAD = 132096 + 69632 + 16384 + 256;  // 218368 (CHUNK=128)
    const int SZ_T1   = 33792  + 36864 + 16384 + 256;  // 87296  (CHUNK=64)
    const int SZ_T2   = 9216   + 36864 + 16384 + 256;  // 62720  (CHUNK=64)
    const int SZ_T3   = 3072   + 12288 + 16384 + 256;  // 32000  (CHUNK=16)

    static bool attr_done = false;
    if (!attr_done) {
        cudaFuncSetAttribute(vocab_kernel<1024>,
            cudaFuncAttributeMaxDynamicSharedMemorySize, SZ_HEAD);
        cudaFuncSetAttribute(vocab_kernel<256>,
            cudaFuncAttributeMaxDynamicSharedMemorySize, SZ_T1);
        cudaFuncSetAttribute(vocab_kernel<64>,
            cudaFuncAttributeMaxDynamicSharedMemorySize, SZ_T2);
        cudaFuncSetAttribute(vocab_kernel<16>,
            cudaFuncAttributeMaxDynamicSharedMemorySize, SZ_T3);
        attr_done = true;
    }

    zero_kernel<<<16, 256>>>();

    proj_kernel<<<dim3(22, 8), 256>>>(hidden, proj0, proj1, proj2, proj3);

    vocab_kernel<1024><<<313, 128, SZ_HEAD>>>(OFF_H0, head_w, cluster_w,
                                              head_b, cluster_b, 20000, 20003, 0);
    vocab_kernel<256><<<313, 128, SZ_T1>>>(OFF_H1, w1, w1, b1, b1,
                                           20000, 20000, 1);
    vocab_kernel<64><<<2500, 128, SZ_T2>>>(OFF_H2, w2, w2, b2, b2,
                                           160000, 160000, 2);
    vocab_kernel<16><<<1059, 128, SZ_T3>>>(OFF_H3, w3, w3, b3, b3,
                                           67735, 67735, 3);

    finalize_kernel<<<128, 256>>>(target, head_w, head_b, cluster_w, cluster_b,
                                  w1, b1, w2, b2, w3, b3, out);
}

// round 6
// speedup vs baseline: 1.1286x; 1.1286x over previous
#include <cuda_runtime.h>
#include <cuda_bf16.h>
#include <mma.h>

using namespace nvcuda;
typedef __nv_bfloat16 bf16;

#define OFF_H0 0
#define OFF_H1 1048576            // 1024*1024
#define OFF_H2 1310720            // +1024*256
#define OFF_H3 1376256            // +1024*64

// scratch (static device memory; no allocations anywhere)
__device__ bf16  g_H[1392640];
__device__ float g_sumexp[4096];

__global__ void zero_kernel() {
    int i = blockIdx.x * blockDim.x + threadIdx.x;
    if (i < 4096) g_sumexp[i] = 0.0f;
}

// ---------------------------------------------------------------------------
// cp.async helpers
// ---------------------------------------------------------------------------
__device__ __forceinline__ void cp16(bf16* dst, const bf16* src) {
    unsigned d = (unsigned)__cvta_generic_to_shared(dst);
    asm volatile("cp.async.cg.shared.global [%0], [%1], 16;" :: "r"(d), "l"(src));
}
#define CP_COMMIT() asm volatile("cp.async.commit_group;")
#define CP_WAIT0()  asm volatile("cp.async.wait_group 0;")

// ---------------------------------------------------------------------------
// Unified vocab GEMM + fused exp-sum.
//   Block: NB vocab rows (weight slab resident in smem, bf16, loaded once),
//          loops all 8 m-tiles of 128 tokens.
//   A (=H, bf16) streamed per 128-row x CHUNK chunk via cp.async (2 stages).
//   256 threads = 8 warps.
//     NB=128: warps 2m x 4n, warp tile 64x32 (acc[4][2])
//     NB=64 : warps 4m x 2n, warp tile 32x32 (acc[2][2])
//   Epilogue: per-warp 32x16 patches (j-split), exp+bias, atomicAdd per row.
// smem: Bs[NB*KP] | As0 | As1 [128*APC each] | Cp[8*32*16 f32] | bias[NB]
// ---------------------------------------------------------------------------
template<int K, int NB>
__global__ __launch_bounds__(256, (NB == 64) ? 1 : 2) void vocab_kernel(
        int h_off, const float* __restrict__ W, const float* __restrict__ W2,
        const float* __restrict__ bias, const float* __restrict__ bias2,
        int split, int V, int cidx)
{
    constexpr int KP    = K + 8;
    constexpr int CHUNK = (K >= 128) ? 128 : K;   // 128,128,64,16
    constexpr int NC    = K / CHUNK;              // 8, 2, 1, 1
    constexpr int APC   = CHUNK + 8;
    constexpr int VR    = CHUNK / 8;              // 16B vectors per row
    constexpr int VPT   = 128 * VR / 256;         // vectors per thread
    constexpr int WN    = (NB == 128) ? 4 : 2;
    constexpr int TM    = (NB == 128) ? 64 : 32;
    constexpr int FM    = TM / 16;

    extern __shared__ __align__(16) char smem[];
    bf16*  Bs     = (bf16*)smem;
    bf16*  As0    = Bs + NB * KP;
    bf16*  As1    = As0 + 128 * APC;
    float* Cp     = (float*)(As1 + 128 * APC);
    float* bias_s = Cp + 8 * 32 * 16;

    const int tid = threadIdx.x, warpId = tid >> 5, lane = tid & 31;
    const int wm = warpId / WN, wn = warpId % WN;
    const int n0 = blockIdx.x * NB;
    const bf16* __restrict__ H = g_H + h_off;

    auto cp_chunk = [&](bf16* As, int mt, int kc) {
        const bf16* src = H + (size_t)(mt * 128) * K + kc * CHUNK;
        #pragma unroll
        for (int i = 0; i < VPT; i++) {
            int idx = tid + i * 256;
            int r = idx / VR, q = idx % VR;
            cp16(As + r * APC + q * 8, src + (size_t)r * K + q * 8);
        }
    };

    // prologue: chunk (0,0) in flight while we build the weight slab
    cp_chunk(As0, 0, 0);
    CP_COMMIT();

    if (tid < NB) {
        int v = n0 + tid;
        float bv = 0.0f;
        if (v < split)  bv = bias[v];
        else if (v < V) bv = bias2[v - split];
        bias_s[tid] = bv;
    }
    // weight slab: fp32 -> bf16, once per block
    for (int idx = tid; idx < NB * K / 4; idx += 256) {
        int r = idx / (K / 4), q = idx % (K / 4);
        int v = n0 + r;
        float4 val = make_float4(0.f, 0.f, 0.f, 0.f);
        if (v < split)  val = *(const float4*)(W + (size_t)v * K + q * 4);
        else if (v < V) val = *(const float4*)(W2 + (size_t)(v - split) * K + q * 4);
        __nv_bfloat162 lo = __floats2bfloat162_rn(val.x, val.y);
        __nv_bfloat162 hi = __floats2bfloat162_rn(val.z, val.w);
        uint2 pk; pk.x = *(unsigned*)&lo; pk.y = *(unsigned*)&hi;
        *(uint2*)(Bs + r * KP + q * 4) = pk;
    }

    int pb = 0;   // parity of current chunk buffer
    for (int mt = 0; mt < 8; mt++) {
        wmma::fragment<wmma::accumulator, 16, 16, 16, float> acc[FM][2];
        #pragma unroll
        for (int i = 0; i < FM; i++)
            #pragma unroll
            for (int j = 0; j < 2; j++) wmma::fill_fragment(acc[i][j], 0.0f);

        for (int kc = 0; kc < NC; kc++) {
            CP_WAIT0();
            __syncthreads();   // chunk (mt,kc) in buf[pb] ready; prior mma done

            if (kc + 1 < NC)      cp_chunk(pb ? As0 : As1, mt, kc + 1);
            else if (mt + 1 < 8)  cp_chunk(pb ? As0 : As1, mt + 1, 0);
            CP_COMMIT();

            const bf16* As = pb ? As1 : As0;
            #pragma unroll
            for (int kk = 0; kk < CHUNK; kk += 16) {
                wmma::fragment<wmma::matrix_a, 16, 16, 16, bf16, wmma::row_major> af[FM];
                wmma::fragment<wmma::matrix_b, 16, 16, 16, bf16, wmma::col_major> bfr[2];
                #pragma unroll
                for (int i = 0; i < FM; i++)
                    wmma::load_matrix_sync(af[i], As + (wm * TM + i * 16) * APC + kk, APC);
                #pragma unroll
                for (int j = 0; j < 2; j++)
                    wmma::load_matrix_sync(bfr[j],
                        Bs + (wn * 32 + j * 16) * KP + kc * CHUNK + kk, KP);
                #pragma unroll
                for (int i = 0; i < FM; i++)
                    #pragma unroll
                    for (int j = 0; j < 2; j++)
                        wmma::mma_sync(acc[i][j], af[i], bfr[j], acc[i][j]);
            }
            pb ^= 1;
        }

        // epilogue: per-warp 32x16 patch, j-split; conflict-free swizzle
        float* cp = Cp + warpId * 32 * 16;
        #pragma unroll
        for (int h = 0; h < FM / 2; h++) {
            float s = 0.0f;
            #pragma unroll
            for (int j = 0; j < 2; j++) {
                wmma::store_matrix_sync(cp,           acc[2*h+0][j], 16, wmma::mem_row_major);
                wmma::store_matrix_sync(cp + 16 * 16, acc[2*h+1][j], 16, wmma::mem_row_major);
                __syncwarp();
                #pragma unroll
                for (int c = 0; c < 16; c++) {
                    int cc = (c + (lane >> 1)) & 15;
                    int col = wn * 32 + j * 16 + cc;
                    int v = n0 + col;
                    if (v < V) s += __expf(cp[lane * 16 + cc] + bias_s[col]);
                }
                __syncwarp();
            }
            int row_g = mt * 128 + wm * TM + h * 32 + lane;
            atomicAdd(&g_sumexp[cidx * 1024 + row_g], s);
        }
    }
}

// ---------------------------------------------------------------------------
// Fused projection GEMM: 22 n-tiles across the 4 projections, 8 m-tiles.
// H[m,n] = sum_k hidden[m,k] * proj[k,n]; bf16 out to g_H.
// ---------------------------------------------------------------------------
#define AP 40
#define BPP 72
#define CPJ 68

__global__ __launch_bounds__(256) void proj_kernel(const float* __restrict__ A,
        const float* __restrict__ P0, const float* __restrict__ P1,
        const float* __restrict__ P2, const float* __restrict__ P3)
{
    __shared__ __align__(16) float s_c[128 * CPJ];
    bf16* As = (bf16*)s_c;
    bf16* Bs = As + 128 * AP;

    int bx = blockIdx.x;
    const float* B; int Nout, h_off, n0;
    if (bx < 16)       { B = P0; Nout = 1024; h_off = OFF_H0; n0 = bx * 64; }
    else if (bx < 20)  { B = P1; Nout = 256;  h_off = OFF_H1; n0 = (bx - 16) * 64; }
    else if (bx == 20) { B = P2; Nout = 64;   h_off = OFF_H2; n0 = 0; }
    else               { B = P3; Nout = 16;   h_off = OFF_H3; n0 = 0; }

    const int tid = threadIdx.x;
    const int warpId = tid >> 5;
    const int wm = warpId & 3, wn = warpId >> 2;
    const int m0 = blockIdx.y * 128;
    const int K = 1024;

    wmma::fragment<wmma::accumulator, 16, 16, 16, float> acc[2][2];
    #pragma unroll
    for (int i = 0; i < 2; i++)
        #pragma unroll
        for (int j = 0; j < 2; j++) wmma::fill_fragment(acc[i][j], 0.0f);

    for (int kt = 0; kt < K; kt += 32) {
        #pragma unroll
        for (int i = 0; i < 4; i++) {
            int idx = tid + i * 256;
            int r = idx >> 3, kq = (idx & 7) << 2;
            float4 v = *(const float4*)(A + (size_t)(m0 + r) * K + kt + kq);
            bf16* d = As + r * AP + kq;
            d[0] = __float2bfloat16(v.x); d[1] = __float2bfloat16(v.y);
            d[2] = __float2bfloat16(v.z); d[3] = __float2bfloat16(v.w);
        }
        #pragma unroll
        for (int i = 0; i < 2; i++) {
            int idx = tid + i * 256;
            int kr = idx >> 4, nq = (idx & 15) << 2;
            int n = n0 + nq;
            float4 v = make_float4(0.f, 0.f, 0.f, 0.f);
            if (n < Nout) v = *(const float4*)(B + (size_t)(kt + kr) * Nout + n);
            bf16* d = Bs + kr * BPP + nq;
            d[0] = __float2bfloat16(v.x); d[1] = __float2bfloat16(v.y);
            d[2] = __float2bfloat16(v.z); d[3] = __float2bfloat16(v.w);
        }
        __syncthreads();
        #pragma unroll
        for (int kk = 0; kk < 32; kk += 16) {
            wmma::fragment<wmma::matrix_a, 16, 16, 16, bf16, wmma::row_major> af[2];
            wmma::fragment<wmma::matrix_b, 16, 16, 16, bf16, wmma::row_major> bfr[2];
            #pragma unroll
            for (int i = 0; i < 2; i++)
                wmma::load_matrix_sync(af[i], As + (wm * 32 + i * 16) * AP + kk, AP);
            #pragma unroll
            for (int j = 0; j < 2; j++)
                wmma::load_matrix_sync(bfr[j], Bs + kk * BPP + wn * 32 + j * 16, BPP);
            #pragma unroll
            for (int i = 0; i < 2; i++)
                #pragma unroll
                for (int j = 0; j < 2; j++)
                    wmma::mma_sync(acc[i][j], af[i], bfr[j], acc[i][j]);
        }
        __syncthreads();
    }

    #pragma unroll
    for (int i = 0; i < 2; i++)
        #pragma unroll
        for (int j = 0; j < 2; j++)
            wmma::store_matrix_sync(s_c + (wm * 32 + i * 16) * CPJ + wn * 32 + j * 16,
                                    acc[i][j], CPJ, wmma::mem_row_major);
    __syncthreads();

    bf16* H = g_H + h_off;
    for (int idx = tid; idx < 128 * 64; idx += 256) {
        int r = idx >> 6, c = idx & 63;
        int n = n0 + c;
        if (n < Nout)
            H[(size_t)(m0 + r) * Nout + n] = __float2bfloat16(s_c[r * CPJ + c]);
    }
}

// ---------------------------------------------------------------------------
// Finalize: per-row target logit + combine with logsumexps. One warp per row.
// ---------------------------------------------------------------------------
__device__ __forceinline__ float wdot(const bf16* h, const float* w, int K, int lane) {
    float s = 0.0f;
    for (int k = lane; k < K; k += 32)
        s += __bfloat162float(h[k]) * w[k];
    #pragma unroll
    for (int o = 16; o; o >>= 1) s += __shfl_xor_sync(0xffffffffu, s, o);
    return s;
}

__global__ __launch_bounds__(256) void finalize_kernel(const int* __restrict__ target,
    const float* __restrict__ head_w,   const float* __restrict__ head_b,
    const float* __restrict__ cluster_w, const float* __restrict__ cluster_b,
    const float* __restrict__ w1, const float* __restrict__ b1,
    const float* __restrict__ w2, const float* __restrict__ b2,
    const float* __restrict__ w3, const float* __restrict__ b3,
    float* __restrict__ out)
{
    int warpId = threadIdx.x >> 5, lane = threadIdx.x & 31;
    int row = blockIdx.x * 8 + warpId;
    if (row >= 1024) return;

    const bf16* h0 = g_H + (size_t)row * 1024;

    float cl[3];
    #pragma unroll
    for (int j = 0; j < 3; j++)
        cl[j] = wdot(h0, cluster_w + j * 1024, 1024, lane) + cluster_b[j];

    float lse0 = logf(g_sumexp[row]);
    int t = target[row];
    float lp;
    if (t < 20000) {
        float s = wdot(h0, head_w + (size_t)t * 1024, 1024, lane) + head_b[t];
        lp = s - lse0;
    } else if (t < 40000) {
        int ti = t - 20000;
        const bf16* h = g_H + OFF_H1 + (size_t)row * 256;
        float s = wdot(h, w1 + (size_t)ti * 256, 256, lane) + b1[ti];
        lp = (cl[2] - lse0) + (s - logf(g_sumexp[1024 + row]));
    } else if (t < 200000) {
        int ti = t - 40000;
        const bf16* h = g_H + OFF_H2 + (size_t)row * 64;
        float s = wdot(h, w2 + (size_t)ti * 64, 64, lane) + b2[ti];
        lp = (cl[1] - lse0) + (s - logf(g_sumexp[2048 + row]));
    } else {
        int ti = t - 200000;
        const bf16* h = g_H + OFF_H3 + (size_t)row * 16;
        float s = wdot(h, w3 + (size_t)ti * 16, 16, lane) + b3[ti];
        lp = (cl[0] - lse0) + (s - logf(g_sumexp[3072 + row]));
    }
    if (lane == 0) out[row] = -lp;
}

// ---------------------------------------------------------------------------
extern "C" void kernel_launch(void* const* d_in, const int* in_sizes, int n_in,
                              void* d_out, int out_size)
{
    const float* hidden    = (const float*)d_in[0];
    const int*   target    = (const int*)  d_in[1];
    const float* head_w    = (const float*)d_in[2];
    const float* head_b    = (const float*)d_in[3];
    const float* cluster_w = (const float*)d_in[4];
    const float* cluster_b = (const float*)d_in[5];
    const float* proj0     = (const float*)d_in[6];
    const float* proj1     = (const float*)d_in[7];
    const float* proj2     = (const float*)d_in[8];
    const float* proj3     = (const float*)d_in[9];
    const float* w1        = (const float*)d_in[10];
    const float* b1        = (const float*)d_in[11];
    const float* w2        = (const float*)d_in[12];
    const float* b2        = (const float*)d_in[13];
    const float* w3        = (const float*)d_in[14];
    const float* b3        = (const float*)d_in[15];
    float* out = (float*)d_out;

    // dynamic smem: Bs(NB*(K+8)*2) + As(2*128*(CHUNK+8)*2) + Cp(16384) + bias(NB*4)
    const int SZ_HEAD = 64 * 1032 * 2  + 2 * 128 * 136 * 2 + 16384 + 256;  // 218368
    const int SZ_T1   = 128 * 264 * 2  + 2 * 128 * 136 * 2 + 16384 + 512;  // 154112
    const int SZ_T2   = 128 * 72 * 2   + 2 * 128 * 72 * 2  + 16384 + 512;  // 72192
    const int SZ_T3   = 128 * 24 * 2   + 2 * 128 * 24 * 2  + 16384 + 512;  // 35328

    static bool attr_done = false;
    if (!attr_done) {
        cudaFuncSetAttribute((const void*)vocab_kernel<1024, 64>,
            cudaFuncAttributeMaxDynamicSharedMemorySize, SZ_HEAD);
        cudaFuncSetAttribute((const void*)vocab_kernel<256, 128>,
            cudaFuncAttributeMaxDynamicSharedMemorySize, SZ_T1);
        cudaFuncSetAttribute((const void*)vocab_kernel<64, 128>,
            cudaFuncAttributeMaxDynamicSharedMemorySize, SZ_T2);
        cudaFuncSetAttribute((const void*)vocab_kernel<16, 128>,
            cudaFuncAttributeMaxDynamicSharedMemorySize, SZ_T3);
        attr_done = true;
    }

    zero_kernel<<<16, 256>>>();

    proj_kernel<<<dim3(22, 8), 256>>>(hidden, proj0, proj1, proj2, proj3);

    vocab_kernel<1024, 64><<<313, 256, SZ_HEAD>>>(OFF_H0, head_w, cluster_w,
                                                  head_b, cluster_b, 20000, 20003, 0);
    vocab_kernel<256, 128><<<157, 256, SZ_T1>>>(OFF_H1, w1, w1, b1, b1,
                                                20000, 20000, 1);
    vocab_kernel<64, 128><<<1250, 256, SZ_T2>>>(OFF_H2, w2, w2, b2, b2,
                                                160000, 160000, 2);
    vocab_kernel<16, 128><<<530, 256, SZ_T3>>>(OFF_H3, w3, w3, b3, b3,
                                               67735, 67735, 3);

    finalize_kernel<<<128, 256>>>(target, head_w, head_b, cluster_w, cluster_b,
                                  w1, b1, w2, b2, w3, b3, out);
}